// round 3
// baseline (speedup 1.0000x reference)
#include <cuda_runtime.h>

// DynamicRouting: N=64, C=4, H=W=256 fp32. Two-pass, HBM-bound (469 MB).
// Pass1 and Pass2 use IDENTICAL block footprints; pass2 runs in exact reverse
// of pass1's launch order to harvest L2 recency (134MB inputs vs ~126MB L2).

#define HW   65536
#define HW4  16384
#define NSMP 64

__device__ float g_part[NSMP * 512];   // [n][k(0-3:x,4-7:y)][bx] partial sums
__device__ float g_coef[NSMP * 112];   // per-sample folded coefficients

// ---------------------------------------------------------------------------
// Pass 1: grid (64,64), 256 thr. Block (bx,n) reads x[n,c,seg] & y[n,c,seg]
// (same 32KB footprint as the pass-2 block that will re-read it).
// Default caching: leave lines resident in L2 for pass 2.
// ---------------------------------------------------------------------------
__global__ void __launch_bounds__(256)
sum_kernel(const float* __restrict__ x, const float* __restrict__ y) {
    int n = blockIdx.y, bx = blockIdx.x, t = threadIdx.x;
    int pid = bx * 256 + t;

    const float4* xb = (const float4*)(x + (size_t)n * 4 * HW);
    const float4* yb = (const float4*)(y + (size_t)n * 4 * HW);

    float s[8];
    #pragma unroll
    for (int c = 0; c < 4; c++) {
        float4 vx = xb[(size_t)c * HW4 + pid];
        float4 vy = yb[(size_t)c * HW4 + pid];
        s[c]     = (vx.x + vx.y) + (vx.z + vx.w);
        s[4 + c] = (vy.x + vy.y) + (vy.z + vy.w);
    }

    // warp reduce all 8 partials
    #pragma unroll
    for (int o = 16; o > 0; o >>= 1) {
        #pragma unroll
        for (int k = 0; k < 8; k++)
            s[k] += __shfl_down_sync(0xffffffffu, s[k], o);
    }

    __shared__ float ws[8][8];   // [warp][k]
    if ((t & 31) == 0) {
        #pragma unroll
        for (int k = 0; k < 8; k++) ws[t >> 5][k] = s[k];
    }
    __syncthreads();
    if (t < 8) {
        float acc = 0.f;
        #pragma unroll
        for (int w = 0; w < 8; w++) acc += ws[w][t];
        g_part[n * 512 + t * 64 + bx] = acc;
    }
}

// ---------------------------------------------------------------------------
// Gate kernel: 512 threads. Phase A: reduce the 64 partials per (n,k).
// Phase B (threads 0..63): tiny MLP, threshold, fold masks into coefficients.
// Coef layout per sample (112 floats):
//   [0..15] Ax=mx0*w_e1  [16..31] Ay=my0*w_e3  [32..35] bx=mx0*b_e1+my0*b_e3
//   [36..67] Bx=mx1*w_e2 [68..99] By=my1*w_e4  [100..107] by=mx1*b_e2+my1*b_e4
// ---------------------------------------------------------------------------
__global__ void __launch_bounds__(512)
gate_kernel(const float* __restrict__ w_rf1, const float* __restrict__ b_rf1,
            const float* __restrict__ w_rf2, const float* __restrict__ b_rf2,
            const float* __restrict__ w_e1,  const float* __restrict__ b_e1,
            const float* __restrict__ w_e2,  const float* __restrict__ b_e2,
            const float* __restrict__ w_e3,  const float* __restrict__ b_e3,
            const float* __restrict__ w_e4,  const float* __restrict__ b_e4) {
    __shared__ float red[512];   // [n*8 + k]
    int t = threadIdx.x;
    {
        int n = t >> 3, k = t & 7;
        const float* p = g_part + n * 512 + k * 64;
        float acc = 0.f;
        #pragma unroll
        for (int i = 0; i < 64; i++) acc += p[i];
        red[n * 8 + k] = acc;
    }
    __syncthreads();

    if (t >= NSMP) return;
    int n = t;
    const float inv = 1.0f / (float)HW;

    float px[4], py[4];
    #pragma unroll
    for (int c = 0; c < 4; c++) {
        px[c] = red[n * 8 + c] * inv;
        py[c] = red[n * 8 + 4 + c] * inv;
    }

    float gx1[2], gy1[2];
    #pragma unroll
    for (int j = 0; j < 2; j++) {
        float ax = b_rf1[j], ay = b_rf1[j];
        #pragma unroll
        for (int c = 0; c < 4; c++) {
            ax += px[c] * w_rf1[j * 4 + c];
            ay += py[c] * w_rf1[j * 4 + c];
        }
        gx1[j] = ax; gy1[j] = ay;
    }
    float gx[2], gy[2];
    #pragma unroll
    for (int i = 0; i < 2; i++) {
        float ax = b_rf2[i], ay = b_rf2[i];
        #pragma unroll
        for (int j = 0; j < 2; j++) {
            ax += gx1[j] * w_rf2[i * 2 + j];
            ay += gy1[j] * w_rf2[i * 2 + j];
        }
        gx[i] = ax; gy[i] = ay;
    }

    float mx0 = gx[0] > 0.f ? 1.f : 0.f;
    float mx1 = gx[1] > 0.f ? 1.f : 0.f;
    float my0 = gy[0] > 0.f ? 1.f : 0.f;
    float my1 = gy[1] > 0.f ? 1.f : 0.f;

    float* cf = g_coef + n * 112;
    #pragma unroll
    for (int i = 0; i < 16; i++) {
        cf[i]      = mx0 * w_e1[i];
        cf[16 + i] = my0 * w_e3[i];
    }
    #pragma unroll
    for (int o = 0; o < 4; o++)
        cf[32 + o] = mx0 * b_e1[o] + my0 * b_e3[o];
    #pragma unroll
    for (int i = 0; i < 32; i++) {
        cf[36 + i] = mx1 * w_e2[i];
        cf[68 + i] = my1 * w_e4[i];
    }
    #pragma unroll
    for (int o = 0; o < 8; o++)
        cf[100 + o] = mx1 * b_e2[o] + my1 * b_e4[o];
}

// ---------------------------------------------------------------------------
// Pass 2: grid (64,64), 256 thr. Block index REVERSED relative to pass 1 so
// the earliest pass-2 blocks re-read the most recently resident L2 lines.
// __ldcs/__stcs: evict-first so pass-2 traffic doesn't flush resident input.
// ---------------------------------------------------------------------------
__global__ void __launch_bounds__(256)
main_kernel(const float* __restrict__ x, const float* __restrict__ y,
            float* __restrict__ out) {
    int n  = 63 - blockIdx.y;            // reverse of pass-1 launch order
    int bx = 63 - blockIdx.x;
    int pid = bx * 256 + threadIdx.x;

    __shared__ float cf[112];
    if (threadIdx.x < 112) cf[threadIdx.x] = g_coef[n * 112 + threadIdx.x];
    __syncthreads();

    const float4* xb = (const float4*)(x + (size_t)n * 4 * HW);
    const float4* yb = (const float4*)(y + (size_t)n * 4 * HW);

    float4 xv[4], yv[4];
    #pragma unroll
    for (int c = 0; c < 4; c++) {
        xv[c] = __ldcs(xb + (size_t)c * HW4 + pid);
        yv[c] = __ldcs(yb + (size_t)c * HW4 + pid);
    }

    // out_x: 4 channels
    float4* ox = (float4*)(out + (size_t)n * 4 * HW);
    #pragma unroll
    for (int o = 0; o < 4; o++) {
        float b = cf[32 + o];
        float4 acc = make_float4(b, b, b, b);
        #pragma unroll
        for (int c = 0; c < 4; c++) {
            float a1 = cf[o * 4 + c];
            float a2 = cf[16 + o * 4 + c];
            acc.x += a1 * xv[c].x + a2 * yv[c].x;
            acc.y += a1 * xv[c].y + a2 * yv[c].y;
            acc.z += a1 * xv[c].z + a2 * yv[c].z;
            acc.w += a1 * xv[c].w + a2 * yv[c].w;
        }
        __stcs(ox + (size_t)o * HW4 + pid, acc);
    }

    // out_y: 8 channels, after the out_x block
    float4* oy = (float4*)(out + (size_t)NSMP * 4 * HW + (size_t)n * 8 * HW);
    #pragma unroll
    for (int o = 0; o < 8; o++) {
        float b = cf[100 + o];
        float4 acc = make_float4(b, b, b, b);
        #pragma unroll
        for (int c = 0; c < 4; c++) {
            float a1 = cf[36 + o * 4 + c];
            float a2 = cf[68 + o * 4 + c];
            acc.x += a1 * xv[c].x + a2 * yv[c].x;
            acc.y += a1 * xv[c].y + a2 * yv[c].y;
            acc.z += a1 * xv[c].z + a2 * yv[c].z;
            acc.w += a1 * xv[c].w + a2 * yv[c].w;
        }
        __stcs(oy + (size_t)o * HW4 + pid, acc);
    }
}

// ---------------------------------------------------------------------------
extern "C" void kernel_launch(void* const* d_in, const int* in_sizes, int n_in,
                              void* d_out, int out_size) {
    const float* x = (const float*)d_in[0];
    const float* y = (const float*)d_in[1];

    dim3 grid(64, 64);
    sum_kernel<<<grid, 256>>>(x, y);

    gate_kernel<<<1, 512>>>((const float*)d_in[2],  (const float*)d_in[3],
                            (const float*)d_in[4],  (const float*)d_in[5],
                            (const float*)d_in[6],  (const float*)d_in[7],
                            (const float*)d_in[8],  (const float*)d_in[9],
                            (const float*)d_in[10], (const float*)d_in[11],
                            (const float*)d_in[12], (const float*)d_in[13]);

    main_kernel<<<grid, 256>>>(x, y, (float*)d_out);
}